// round 11
// baseline (speedup 1.0000x reference)
#include <cuda_runtime.h>
#include <cstdint>

#define BB 2048
#define TT 512
#define KK 32
#define CH 32
#define FULLM 0xffffffffu

// 128 MB alpha-row scratch (device global; no allocation)
__device__ float g_alpha[(size_t)BB * TT * KK];

// ---- packed f32x2 helpers
__device__ __forceinline__ unsigned long long add2(unsigned long long a, unsigned long long b) {
    unsigned long long r; asm("add.rn.f32x2 %0,%1,%2;" : "=l"(r) : "l"(a), "l"(b)); return r;
}
__device__ __forceinline__ unsigned long long fma2(unsigned long long a, unsigned long long b, unsigned long long c) {
    unsigned long long r; asm("fma.rn.f32x2 %0,%1,%2,%3;" : "=l"(r) : "l"(a), "l"(b), "l"(c)); return r;
}
__device__ __forceinline__ float2 unpk(unsigned long long a) {
    float2 f; asm("mov.b64 {%0,%1},%2;" : "=f"(f.x), "=f"(f.y) : "l"(a)); return f;
}
__device__ __forceinline__ unsigned long long pk(float x, float y) {
    unsigned long long r; asm("mov.b64 %0,{%1,%2};" : "=l"(r) : "f"(x), "f"(y)); return r;
}

// warp-wide max (all lanes get result)
__device__ __forceinline__ float wmax(float v) {
#pragma unroll
    for (int o = 16; o; o >>= 1)
        v = fmaxf(v, __shfl_xor_sync(FULLM, v, o));
    return v;
}
// warp-wide sum
__device__ __forceinline__ float wsum(float v) {
#pragma unroll
    for (int o = 16; o; o >>= 1)
        v += __shfl_xor_sync(FULLM, v, o);
    return v;
}

// max_i (row[i] + trc[i][lane]) using packed adds
// r2[c] = row[4c..4c+3] -> trc2[2c],2c+1 ; r2[c+4] = row[4c+16..] -> trc2[2c+8],2c+9
__device__ __forceinline__ float rowmax(const float* __restrict__ row,
                                        const unsigned long long* __restrict__ trc2) {
    const ulonglong2* r2 = reinterpret_cast<const ulonglong2*>(row);
    float best = -3.402823466e38f;
#pragma unroll
    for (int c = 0; c < 4; c++) {
        ulonglong2 qa = r2[c];
        ulonglong2 qb = r2[c + 4];
        float2 f0 = unpk(add2(qa.x, trc2[2 * c + 0]));
        float2 f1 = unpk(add2(qa.y, trc2[2 * c + 1]));
        float2 f2 = unpk(add2(qb.x, trc2[2 * c + 8]));
        float2 f3 = unpk(add2(qb.y, trc2[2 * c + 9]));
        float m0 = fmaxf(fmaxf(f0.x, f0.y), fmaxf(f1.x, f1.y));
        float m1 = fmaxf(fmaxf(f2.x, f2.y), fmaxf(f3.x, f3.y));
        best = fmaxf(best, fmaxf(m0, m1));
    }
    return best;
}

// sum_i row[i] * etr[i][lane] using packed FMAs
__device__ __forceinline__ float rowdot(const float* __restrict__ row,
                                        const unsigned long long* __restrict__ etr2) {
    const ulonglong2* r2 = reinterpret_cast<const ulonglong2*>(row);
    unsigned long long a0 = 0ull, a1 = 0ull, a2 = 0ull, a3 = 0ull;
#pragma unroll
    for (int c = 0; c < 4; c++) {
        ulonglong2 qa = r2[c];
        ulonglong2 qb = r2[c + 4];
        a0 = fma2(qa.x, etr2[2 * c + 0], a0);
        a1 = fma2(qa.y, etr2[2 * c + 1], a1);
        a2 = fma2(qb.x, etr2[2 * c + 8], a2);
        a3 = fma2(qb.y, etr2[2 * c + 9], a3);
    }
    float2 s = unpk(add2(add2(a0, a1), add2(a2, a3)));
    return s.x + s.y;
}

// exact power-of-2 renormalization
__device__ __forceinline__ void renorm(float& a, int& C) {
    int eb = (__float_as_int(a) >> 23) & 0xff;
#pragma unroll
    for (int o = 16; o; o >>= 1)
        eb = max(eb, __shfl_xor_sync(FULLM, eb, o));
    int de = eb - 127;
    C += de;
    a *= __int_as_float((127 - de) << 23);
}

__global__ __launch_bounds__(64, 8)
void crf_fused_kernel(const float* __restrict__ pot,     // [B,T,K]
                      const float* __restrict__ trans,   // [K,K]
                      const int*   __restrict__ seqlen,  // [B]
                      const int*   __restrict__ tags_in, // [B,T]
                      float*       __restrict__ out)     // [B*T + 2B] f32
{
    __shared__ float Trp[KK * 33];                        // Trp[row*33+col] = trans[row][col]
    __shared__ __align__(16) float vrow[4][KK];
    __shared__ __align__(16) float lrow[4][KK];
    __shared__ float btrows[2][CH * KK];

    const int tid  = threadIdx.x;
    const int lane = tid & 31;
    const int role = tid >> 5;             // 0 = viterbi, 1 = partition
    const int b0   = blockIdx.x * 2;
    const int b1   = b0 + 1;
    const int len0 = seqlen[b0];
    const int len1 = seqlen[b1];

    const float LOG2E = 1.4426950408889634f;
    const float* pb0 = pot + (size_t)b0 * TT * KK;
    const float* pb1 = pot + (size_t)b1 * TT * KK;
    float* out_tags = out;

    for (int idx = tid; idx < KK * KK; idx += 64)
        Trp[(idx >> 5) * 33 + (idx & 31)] = trans[idx];
    __syncthreads();

    const int cm = min(len0, len1);

    if (role == 0) {
        // ===================== Viterbi warp: sequences b0, b1 =====================
        unsigned long long trc2[16];
#pragma unroll
        for (int k = 0; k < 16; k++)
            trc2[k] = pk(__ldg(&trans[(2 * k) * KK + lane]),
                         __ldg(&trans[(2 * k + 1) * KK + lane]));

        float* gab0 = g_alpha + (size_t)b0 * TT * KK;
        float* gab1 = g_alpha + (size_t)b1 * TT * KK;
        float al0 = pb0[lane];
        float al1 = pb1[lane];

        int t = 1;
        for (; t + 1 < cm; t += 2) {
            float pa0 = pb0[(size_t)t * KK + lane];
            float pa1 = pb1[(size_t)t * KK + lane];
            float pc0 = pb0[(size_t)(t + 1) * KK + lane];
            float pc1 = pb1[(size_t)(t + 1) * KK + lane];
            gab0[(size_t)(t - 1) * KK + lane] = al0;
            gab1[(size_t)(t - 1) * KK + lane] = al1;
            vrow[0][lane] = al0; vrow[1][lane] = al1;
            __syncwarp();
            al0 = pa0 + rowmax(vrow[0], trc2);
            al1 = pa1 + rowmax(vrow[1], trc2);
            gab0[(size_t)t * KK + lane] = al0;
            gab1[(size_t)t * KK + lane] = al1;
            vrow[2][lane] = al0; vrow[3][lane] = al1;
            __syncwarp();
            al0 = pc0 + rowmax(vrow[2], trc2);
            al1 = pc1 + rowmax(vrow[3], trc2);
        }
        // tails (warp-uniform loops)
        for (int q = t; q < len0; q++) {
            float pa = pb0[(size_t)q * KK + lane];
            gab0[(size_t)(q - 1) * KK + lane] = al0;
            vrow[0][lane] = al0;
            __syncwarp();
            al0 = pa + rowmax(vrow[0], trc2);
            __syncwarp();
        }
        for (int q = t; q < len1; q++) {
            float pa = pb1[(size_t)q * KK + lane];
            gab1[(size_t)(q - 1) * KK + lane] = al1;
            vrow[1][lane] = al1;
            __syncwarp();
            al1 = pa + rowmax(vrow[1], trc2);
            __syncwarp();
        }

        // last tags: warp-max + ballot (exact first-occurrence)
        float mv0 = wmax(al0);
        float mv1 = wmax(al1);
        int last0 = __ffs(__ballot_sync(FULLM, al0 == mv0)) - 1;
        int last1 = __ffs(__ballot_sync(FULLM, al1 == mv1)) - 1;

        for (int tt = len0 - 1 + lane; tt < TT; tt += 32)
            out_tags[(size_t)b0 * TT + tt] = (float)last0;
        for (int tt = len1 - 1 + lane; tt < TT; tt += 32)
            out_tags[(size_t)b1 * TT + tt] = (float)last1;
        if (lane == 0) {
            out[(size_t)BB * TT + b0] = mv0;
            out[(size_t)BB * TT + b1] = mv1;
        }

        __threadfence_block();
        __syncwarp(FULLM);

        // ---- interleaved backtrace for both sequences
        int j0 = last0, j1 = last1;
        int hi0 = len0 - 2, hi1 = len1 - 2;
        while (hi0 >= 0 || hi1 >= 0) {
            int lo0 = hi0 - (CH - 1); if (lo0 < 0) lo0 = 0;
            int lo1 = hi1 - (CH - 1); if (lo1 < 0) lo1 = 0;
            if (hi0 >= 0)
                for (int k = lane; k < (hi0 - lo0 + 1) * KK; k += 32)
                    btrows[0][k] = gab0[(size_t)lo0 * KK + k];
            if (hi1 >= 0)
                for (int k = lane; k < (hi1 - lo1 + 1) * KK; k += 32)
                    btrows[1][k] = gab1[(size_t)lo1 * KK + k];
            __syncwarp();
            int n0 = (hi0 >= 0) ? (hi0 - lo0 + 1) : 0;
            int n1 = (hi1 >= 0) ? (hi1 - lo1 + 1) : 0;
            int n = max(n0, n1);
            for (int k = 0; k < n; k++) {
                int r0 = (k < n0) ? (hi0 - lo0 - k) : 0;   // clamped: safe smem idx
                int r1 = (k < n1) ? (hi1 - lo1 - k) : 0;
                float s0 = btrows[0][r0 * KK + lane] + Trp[lane * 33 + j0];
                float s1 = btrows[1][r1 * KK + lane] + Trp[lane * 33 + j1];
                float m0 = wmax(s0);
                float m1 = wmax(s1);
                unsigned q0 = __ballot_sync(FULLM, s0 == m0);
                unsigned q1 = __ballot_sync(FULLM, s1 == m1);
                if (k < n0) {                 // warp-uniform condition
                    j0 = __ffs(q0) - 1;
                    if (lane == 0) out_tags[(size_t)b0 * TT + (hi0 - k)] = (float)j0;
                }
                if (k < n1) {
                    j1 = __ffs(q1) - 1;
                    if (lane == 0) out_tags[(size_t)b1 * TT + (hi1 - k)] = (float)j1;
                }
            }
            hi0 = (hi0 >= 0) ? lo0 - 1 : -1;
            hi1 = (hi1 >= 0) ? lo1 - 1 : -1;
            __syncwarp();
        }
    } else {
        // =========== partition (linear domain) + seq-score: b0, b1 ===========
        unsigned long long etr2[16];
#pragma unroll
        for (int k = 0; k < 16; k++)
            etr2[k] = pk(exp2f(__ldg(&trans[(2 * k) * KK + lane]) * LOG2E),
                         exp2f(__ldg(&trans[(2 * k + 1) * KK + lane]) * LOG2E));

        float a0 = exp2f(pb0[lane] * LOG2E);
        float a1 = exp2f(pb1[lane] * LOG2E);
        int C0 = 0, C1 = 0;

        int t = 1;
        for (; t + 1 < cm; t += 2) {
            float pa0 = pb0[(size_t)t * KK + lane];
            float pa1 = pb1[(size_t)t * KK + lane];
            float pc0 = pb0[(size_t)(t + 1) * KK + lane];
            float pc1 = pb1[(size_t)(t + 1) * KK + lane];
            lrow[0][lane] = a0; lrow[1][lane] = a1;
            __syncwarp();
            a0 = exp2f(pa0 * LOG2E) * rowdot(lrow[0], etr2);
            a1 = exp2f(pa1 * LOG2E) * rowdot(lrow[1], etr2);
            lrow[2][lane] = a0; lrow[3][lane] = a1;
            __syncwarp();
            a0 = exp2f(pc0 * LOG2E) * rowdot(lrow[2], etr2);
            a1 = exp2f(pc1 * LOG2E) * rowdot(lrow[3], etr2);
            if (((t + 1) & 7) == 0) { renorm(a0, C0); renorm(a1, C1); }
        }
        for (int q = t; q < len0; q++) {
            float pa = pb0[(size_t)q * KK + lane];
            lrow[0][lane] = a0;
            __syncwarp();
            a0 = exp2f(pa * LOG2E) * rowdot(lrow[0], etr2);
            __syncwarp();
            if ((q & 3) == 3) renorm(a0, C0);
        }
        for (int q = t; q < len1; q++) {
            float pa = pb1[(size_t)q * KK + lane];
            lrow[1][lane] = a1;
            __syncwarp();
            a1 = exp2f(pa * LOG2E) * rowdot(lrow[1], etr2);
            __syncwarp();
            if ((q & 3) == 3) renorm(a1, C1);
        }

        float ln0 = (float)((double)C0 * 0.6931471805599453) + logf(wsum(a0));
        float ln1 = (float)((double)C1 * 0.6931471805599453) + logf(wsum(a1));

        // sequence scores (transitions from smem)
        const int* ti0 = tags_in + (size_t)b0 * TT;
        const int* ti1 = tags_in + (size_t)b1 * TT;
        float ss0 = 0.f, ss1 = 0.f;
        for (int tt = lane; tt < TT; tt += 32) {
            int tg0 = ti0[tt], tg1 = ti1[tt];
            if (tt < len0)     ss0 += pb0[(size_t)tt * KK + tg0];
            if (tt < len0 - 1) ss0 += Trp[tg0 * 33 + ti0[tt + 1]];
            if (tt < len1)     ss1 += pb1[(size_t)tt * KK + tg1];
            if (tt < len1 - 1) ss1 += Trp[tg1 * 33 + ti1[tt + 1]];
        }
        ss0 = wsum(ss0);
        ss1 = wsum(ss1);

        if (lane == 0) {
            out[(size_t)BB * TT + BB + b0] = ss0 - ln0;
            out[(size_t)BB * TT + BB + b1] = ss1 - ln1;
        }
    }
}

extern "C" void kernel_launch(void* const* d_in, const int* in_sizes, int n_in,
                              void* d_out, int out_size) {
    const float* pot    = (const float*)d_in[0];
    const float* trans  = (const float*)d_in[1];
    const int*   seqlen = (const int*)d_in[2];
    const int*   tags   = (const int*)d_in[3];
    float* out = (float*)d_out;

    // 2 sequences per 64-thread block (viterbi warp + partition warp, ILP=2 each)
    crf_fused_kernel<<<BB / 2, 64>>>(pot, trans, seqlen, tags, out);
}

// round 12
// speedup vs baseline: 1.0948x; 1.0948x over previous
#include <cuda_runtime.h>
#include <cstdint>

#define BB 2048
#define TT 512
#define KK 32
#define FULLM 0xffffffffu

// 128 MB alpha-row scratch (device global; no allocation)
__device__ float g_alpha[(size_t)BB * TT * KK];

// ---- packed f32x2 helpers
__device__ __forceinline__ unsigned long long add2(unsigned long long a, unsigned long long b) {
    unsigned long long r; asm("add.rn.f32x2 %0,%1,%2;" : "=l"(r) : "l"(a), "l"(b)); return r;
}
__device__ __forceinline__ unsigned long long fma2(unsigned long long a, unsigned long long b, unsigned long long c) {
    unsigned long long r; asm("fma.rn.f32x2 %0,%1,%2,%3;" : "=l"(r) : "l"(a), "l"(b), "l"(c)); return r;
}
__device__ __forceinline__ float2 unpk(unsigned long long a) {
    float2 f; asm("mov.b64 {%0,%1},%2;" : "=f"(f.x), "=f"(f.y) : "l"(a)); return f;
}
__device__ __forceinline__ unsigned long long pk(float x, float y) {
    unsigned long long r; asm("mov.b64 %0,{%1,%2};" : "=l"(r) : "f"(x), "f"(y)); return r;
}

// order-preserving float->uint transform (exact; total order matches float compare for non-NaN)
__device__ __forceinline__ unsigned ordu(float f) {
    int x = __float_as_int(f);
    return (unsigned)x ^ (unsigned)((x >> 31) | 0x80000000);
}

// exact first-occurrence warp argmax via REDUX + ballot; returns index (all lanes)
__device__ __forceinline__ int wargmax_idx(float s) {
    unsigned u = ordu(s);
    unsigned um = __reduce_max_sync(FULLM, u);
    return __ffs(__ballot_sync(FULLM, u == um)) - 1;
}

// warp-wide sum
__device__ __forceinline__ float wsum(float v) {
#pragma unroll
    for (int o = 16; o; o >>= 1)
        v += __shfl_xor_sync(FULLM, v, o);
    return v;
}

// max_i (row[i] + trc[i][lane]) using packed adds
// r2[c] = row[4c..4c+3] -> trc2[2c],2c+1 ; r2[c+4] = row[4c+16..] -> trc2[2c+8],2c+9
__device__ __forceinline__ float rowmax(const float* __restrict__ row,
                                        const unsigned long long* __restrict__ trc2) {
    const ulonglong2* r2 = reinterpret_cast<const ulonglong2*>(row);
    float best = -3.402823466e38f;
#pragma unroll
    for (int c = 0; c < 4; c++) {
        ulonglong2 qa = r2[c];
        ulonglong2 qb = r2[c + 4];
        float2 f0 = unpk(add2(qa.x, trc2[2 * c + 0]));
        float2 f1 = unpk(add2(qa.y, trc2[2 * c + 1]));
        float2 f2 = unpk(add2(qb.x, trc2[2 * c + 8]));
        float2 f3 = unpk(add2(qb.y, trc2[2 * c + 9]));
        float m0 = fmaxf(fmaxf(f0.x, f0.y), fmaxf(f1.x, f1.y));
        float m1 = fmaxf(fmaxf(f2.x, f2.y), fmaxf(f3.x, f3.y));
        best = fmaxf(best, fmaxf(m0, m1));
    }
    return best;
}

// sum_i row[i] * etr[i][lane] using packed FMAs
__device__ __forceinline__ float rowdot(const float* __restrict__ row,
                                        const unsigned long long* __restrict__ etr2) {
    const ulonglong2* r2 = reinterpret_cast<const ulonglong2*>(row);
    unsigned long long a0 = 0ull, a1 = 0ull, a2 = 0ull, a3 = 0ull;
#pragma unroll
    for (int c = 0; c < 4; c++) {
        ulonglong2 qa = r2[c];
        ulonglong2 qb = r2[c + 4];
        a0 = fma2(qa.x, etr2[2 * c + 0], a0);
        a1 = fma2(qa.y, etr2[2 * c + 1], a1);
        a2 = fma2(qb.x, etr2[2 * c + 8], a2);
        a3 = fma2(qb.y, etr2[2 * c + 9], a3);
    }
    float2 s = unpk(add2(add2(a0, a1), add2(a2, a3)));
    return s.x + s.y;
}

// exact power-of-2 renormalization (REDUX on exponent)
__device__ __forceinline__ void renorm(float& a, int& C) {
    unsigned eb = (unsigned)((__float_as_int(a) >> 23) & 0xff);
    eb = __reduce_max_sync(FULLM, eb);
    int de = (int)eb - 127;
    C += de;
    a *= __int_as_float((127 - de) << 23);
}

__global__ __launch_bounds__(64, 16)
void crf_fused_kernel(const float* __restrict__ pot,     // [B,T,K]
                      const float* __restrict__ trans,   // [K,K]
                      const int*   __restrict__ seqlen,  // [B]
                      const int*   __restrict__ tags_in, // [B,T]
                      float*       __restrict__ out)     // [B*T + 2B] f32
{
    __shared__ float Trp[KK * 33];                     // Trp[row*33+col] = trans[row][col]
    __shared__ __align__(16) float vrow[2][KK];
    __shared__ __align__(16) float lrow[2][KK];

    const int tid  = threadIdx.x;
    const int lane = tid & 31;
    const int role = tid >> 5;          // 0 = viterbi, 1 = partition
    const int b    = blockIdx.x;
    const int len  = seqlen[b];

    const float LOG2E = 1.4426950408889634f;
    const float* pb = pot + (size_t)b * TT * KK;
    float* out_tags = out;

    // padded transitions into smem (both warps), needed by warp0's backtrace
    for (int idx = tid; idx < KK * KK; idx += 64)
        Trp[(idx >> 5) * 33 + (idx & 31)] = trans[idx];
    __syncthreads();

    if (role == 0) {
        // ===================== Viterbi warp =====================
        // packed Tr columns: trc2[k] = (Tr[2k][lane], Tr[2k+1][lane])
        unsigned long long trc2[16];
#pragma unroll
        for (int k = 0; k < 16; k++)
            trc2[k] = pk(__ldg(&trans[(2 * k) * KK + lane]),
                         __ldg(&trans[(2 * k + 1) * KK + lane]));

        float* gab = g_alpha + (size_t)b * TT * KK;
        float alpha = pb[lane];

        int t = 1;
        for (; t + 1 < len; t += 2) {
            float pa = pb[(size_t)t * KK + lane];
            float pc = pb[(size_t)(t + 1) * KK + lane];
            gab[(size_t)(t - 1) * KK + lane] = alpha;
            vrow[0][lane] = alpha;
            __syncwarp();
            alpha = pa + rowmax(vrow[0], trc2);
            gab[(size_t)t * KK + lane] = alpha;
            vrow[1][lane] = alpha;
            __syncwarp();
            alpha = pc + rowmax(vrow[1], trc2);
        }
        if (t < len) {
            float pa = pb[(size_t)t * KK + lane];
            gab[(size_t)(t - 1) * KK + lane] = alpha;
            vrow[0][lane] = alpha;
            __syncwarp();
            alpha = pa + rowmax(vrow[0], trc2);
        }

        // last_tag (first-occurrence) / best_score
        const int last_tag = wargmax_idx(alpha);
        const float bv = __shfl_sync(FULLM, alpha, last_tag);

        for (int tt = len - 1 + lane; tt < TT; tt += 32)
            out_tags[(size_t)b * TT + tt] = (float)last_tag;
        if (lane == 0)
            out[(size_t)BB * TT + b] = bv;

        // lane i reads back only its own alpha elements (same-thread RAW) —
        // no cross-lane global visibility needed; exchange happens via REDUX.
        __syncwarp(FULLM);

        // ---- backtrace with 8-deep LDG register pipeline (no smem staging)
        int j = last_tag;
        const int n = len - 1;              // steps: t = len-2 .. 0
        float pre[8];
#pragma unroll
        for (int d = 0; d < 8; d++) {
            int tr = len - 2 - d;
            pre[d] = (tr >= 0) ? gab[(size_t)tr * KK + lane] : 0.f;
        }
        for (int k0 = 0; k0 < n; k0 += 8) {
#pragma unroll
            for (int d = 0; d < 8; d++) {
                int t2 = len - 2 - (k0 + d);
                if (t2 >= 0) {               // warp-uniform
                    float s = pre[d] + Trp[lane * 33 + j];
                    j = wargmax_idx(s);
                    if (lane == 0)
                        out_tags[(size_t)b * TT + t2] = (float)j;
                    int tn = t2 - 8;
                    pre[d] = (tn >= 0) ? gab[(size_t)tn * KK + lane] : 0.f;
                }
            }
        }
    } else {
        // =========== partition (linear domain) + seq-score warp ===========
        unsigned long long etr2[16];
#pragma unroll
        for (int k = 0; k < 16; k++)
            etr2[k] = pk(exp2f(__ldg(&trans[(2 * k) * KK + lane]) * LOG2E),
                         exp2f(__ldg(&trans[(2 * k + 1) * KK + lane]) * LOG2E));

        float a = exp2f(pb[lane] * LOG2E);   // a_0 = exp(pot_0)
        int C = 0;

        int t = 1;
        for (; t + 1 < len; t += 2) {
            float pa = pb[(size_t)t * KK + lane];
            float pc = pb[(size_t)(t + 1) * KK + lane];
            lrow[0][lane] = a;
            __syncwarp();
            a = exp2f(pa * LOG2E) * rowdot(lrow[0], etr2);
            lrow[1][lane] = a;
            __syncwarp();
            a = exp2f(pc * LOG2E) * rowdot(lrow[1], etr2);
            if (((t + 1) & 7) == 0)
                renorm(a, C);
        }
        if (t < len) {
            float pa = pb[(size_t)t * KK + lane];
            lrow[0][lane] = a;
            __syncwarp();
            a = exp2f(pa * LOG2E) * rowdot(lrow[0], etr2);
        }

        // log_norm = C*ln2 + log(sum_j a_j)
        float s = wsum(a);
        float log_norm = (float)((double)C * 0.6931471805599453) + logf(s);

        // sequence score (gold path; transitions from smem)
        const int* ti = tags_in + (size_t)b * TT;
        float sscore = 0.f;
        for (int tt = lane; tt < TT; tt += 32) {
            int tg = ti[tt];
            if (tt < len)     sscore += pb[(size_t)tt * KK + tg];
            if (tt < len - 1) sscore += Trp[tg * 33 + ti[tt + 1]];
        }
        sscore = wsum(sscore);

        if (lane == 0)
            out[(size_t)BB * TT + BB + b] = sscore - log_norm;
    }
}

extern "C" void kernel_launch(void* const* d_in, const int* in_sizes, int n_in,
                              void* d_out, int out_size) {
    const float* pot    = (const float*)d_in[0];
    const float* trans  = (const float*)d_in[1];
    const int*   seqlen = (const int*)d_in[2];
    const int*   tags   = (const int*)d_in[3];
    float* out = (float*)d_out;

    // one sequence per 64-thread block (viterbi warp + partition warp)
    crf_fused_kernel<<<BB, 64>>>(pot, trans, seqlen, tags, out);
}

// round 13
// speedup vs baseline: 1.2605x; 1.1514x over previous
#include <cuda_runtime.h>
#include <cstdint>

#define BB 2048
#define TT 512
#define KK 32
#define FULLM 0xffffffffu

// 128 MB alpha-row scratch + last-tag handoff (device globals; no allocation)
__device__ float g_alpha[(size_t)BB * TT * KK];
__device__ int   g_last[BB];

// ---- packed f32x2 helpers
__device__ __forceinline__ unsigned long long add2(unsigned long long a, unsigned long long b) {
    unsigned long long r; asm("add.rn.f32x2 %0,%1,%2;" : "=l"(r) : "l"(a), "l"(b)); return r;
}
__device__ __forceinline__ unsigned long long fma2(unsigned long long a, unsigned long long b, unsigned long long c) {
    unsigned long long r; asm("fma.rn.f32x2 %0,%1,%2,%3;" : "=l"(r) : "l"(a), "l"(b), "l"(c)); return r;
}
__device__ __forceinline__ float2 unpk(unsigned long long a) {
    float2 f; asm("mov.b64 {%0,%1},%2;" : "=f"(f.x), "=f"(f.y) : "l"(a)); return f;
}
__device__ __forceinline__ unsigned long long pk(float x, float y) {
    unsigned long long r; asm("mov.b64 %0,{%1,%2};" : "=l"(r) : "f"(x), "f"(y)); return r;
}

__device__ __forceinline__ float wsum(float v) {
#pragma unroll
    for (int o = 16; o; o >>= 1)
        v += __shfl_xor_sync(FULLM, v, o);
    return v;
}

// max_i (row[i] + trc[i][lane]) using packed adds
__device__ __forceinline__ float rowmax(const float* __restrict__ row,
                                        const unsigned long long* __restrict__ trc2) {
    const ulonglong2* r2 = reinterpret_cast<const ulonglong2*>(row);
    float best = -3.402823466e38f;
#pragma unroll
    for (int c = 0; c < 4; c++) {
        ulonglong2 qa = r2[c];
        ulonglong2 qb = r2[c + 4];
        float2 f0 = unpk(add2(qa.x, trc2[2 * c + 0]));
        float2 f1 = unpk(add2(qa.y, trc2[2 * c + 1]));
        float2 f2 = unpk(add2(qb.x, trc2[2 * c + 8]));
        float2 f3 = unpk(add2(qb.y, trc2[2 * c + 9]));
        float m0 = fmaxf(fmaxf(f0.x, f0.y), fmaxf(f1.x, f1.y));
        float m1 = fmaxf(fmaxf(f2.x, f2.y), fmaxf(f3.x, f3.y));
        best = fmaxf(best, fmaxf(m0, m1));
    }
    return best;
}

// sum_i row[i] * etr[i][lane] using packed FMAs
__device__ __forceinline__ float rowdot(const float* __restrict__ row,
                                        const unsigned long long* __restrict__ etr2) {
    const ulonglong2* r2 = reinterpret_cast<const ulonglong2*>(row);
    unsigned long long a0 = 0ull, a1 = 0ull, a2 = 0ull, a3 = 0ull;
#pragma unroll
    for (int c = 0; c < 4; c++) {
        ulonglong2 qa = r2[c];
        ulonglong2 qb = r2[c + 4];
        a0 = fma2(qa.x, etr2[2 * c + 0], a0);
        a1 = fma2(qa.y, etr2[2 * c + 1], a1);
        a2 = fma2(qb.x, etr2[2 * c + 8], a2);
        a3 = fma2(qb.y, etr2[2 * c + 9], a3);
    }
    float2 s = unpk(add2(add2(a0, a1), add2(a2, a3)));
    return s.x + s.y;
}

// exact power-of-2 renormalization (shfl exponent max)
__device__ __forceinline__ void renorm(float& a, int& C) {
    int eb = (__float_as_int(a) >> 23) & 0xff;
#pragma unroll
    for (int o = 16; o; o >>= 1)
        eb = max(eb, __shfl_xor_sync(FULLM, eb, o));
    int de = eb - 127;
    C += de;
    a *= __int_as_float((127 - de) << 23);
}

// =============================== Kernel 1: forward passes ===============================
__global__ __launch_bounds__(64, 13)
void crf_forward_kernel(const float* __restrict__ pot,     // [B,T,K]
                        const float* __restrict__ trans,   // [K,K]
                        const int*   __restrict__ seqlen,  // [B]
                        const int*   __restrict__ tags_in, // [B,T]
                        float*       __restrict__ out)     // [B*T + 2B] f32
{
    __shared__ float Trp[KK * 33];                   // trans for seq-score
    __shared__ __align__(16) float vrow[2][KK];
    __shared__ __align__(16) float lrow[2][KK];

    const int tid  = threadIdx.x;
    const int lane = tid & 31;
    const int role = tid >> 5;          // 0 = viterbi fwd, 1 = partition
    const int b    = blockIdx.x;
    const int len  = seqlen[b];

    const float LOG2E = 1.4426950408889634f;
    const float* pb = pot + (size_t)b * TT * KK;
    float* out_tags = out;

    for (int idx = tid; idx < KK * KK; idx += 64)
        Trp[(idx >> 5) * 33 + (idx & 31)] = trans[idx];
    __syncthreads();

    if (role == 0) {
        // ---------------- Viterbi forward (value-only; alphas streamed) ----------------
        unsigned long long trc2[16];
#pragma unroll
        for (int k = 0; k < 16; k++)
            trc2[k] = pk(__ldg(&trans[(2 * k) * KK + lane]),
                         __ldg(&trans[(2 * k + 1) * KK + lane]));

        float* gab = g_alpha + (size_t)b * TT * KK;
        float alpha = pb[lane];

        int t = 1;
        for (; t + 1 < len; t += 2) {
            float pa = pb[(size_t)t * KK + lane];
            float pc = pb[(size_t)(t + 1) * KK + lane];
            gab[(size_t)(t - 1) * KK + lane] = alpha;
            vrow[0][lane] = alpha;
            __syncwarp();
            alpha = pa + rowmax(vrow[0], trc2);
            gab[(size_t)t * KK + lane] = alpha;
            vrow[1][lane] = alpha;
            __syncwarp();
            alpha = pc + rowmax(vrow[1], trc2);
        }
        if (t < len) {
            float pa = pb[(size_t)t * KK + lane];
            gab[(size_t)(t - 1) * KK + lane] = alpha;
            vrow[0][lane] = alpha;
            __syncwarp();
            alpha = pa + rowmax(vrow[0], trc2);
        }

        // last_tag / best_score: bundled shfl argmax (first-occurrence exact)
        float bv = alpha; int bi = lane;
#pragma unroll
        for (int o = 16; o; o >>= 1) {
            float ov = __shfl_xor_sync(FULLM, bv, o);
            int   oi = __shfl_xor_sync(FULLM, bi, o);
            if (ov > bv || (ov == bv && oi < bi)) { bv = ov; bi = oi; }
        }
        const int last_tag = bi;

        for (int tt = len - 1 + lane; tt < TT; tt += 32)
            out_tags[(size_t)b * TT + tt] = (float)last_tag;
        if (lane == 0) {
            out[(size_t)BB * TT + b] = bv;   // best_score
            g_last[b] = last_tag;            // handoff to backtrace kernel
        }
    } else {
        // ---------------- partition (linear domain) + seq-score ----------------
        unsigned long long etr2[16];
#pragma unroll
        for (int k = 0; k < 16; k++)
            etr2[k] = pk(exp2f(__ldg(&trans[(2 * k) * KK + lane]) * LOG2E),
                         exp2f(__ldg(&trans[(2 * k + 1) * KK + lane]) * LOG2E));

        float a = exp2f(pb[lane] * LOG2E);
        int C = 0;

        int t = 1;
        for (; t + 1 < len; t += 2) {
            float pa = pb[(size_t)t * KK + lane];
            float pc = pb[(size_t)(t + 1) * KK + lane];
            lrow[0][lane] = a;
            __syncwarp();
            a = exp2f(pa * LOG2E) * rowdot(lrow[0], etr2);
            lrow[1][lane] = a;
            __syncwarp();
            a = exp2f(pc * LOG2E) * rowdot(lrow[1], etr2);
            if (((t + 1) & 7) == 0)
                renorm(a, C);
        }
        if (t < len) {
            float pa = pb[(size_t)t * KK + lane];
            lrow[0][lane] = a;
            __syncwarp();
            a = exp2f(pa * LOG2E) * rowdot(lrow[0], etr2);
        }

        float s = wsum(a);
        float log_norm = (float)((double)C * 0.6931471805599453) + logf(s);

        const int* ti = tags_in + (size_t)b * TT;
        float sscore = 0.f;
        for (int tt = lane; tt < TT; tt += 32) {
            int tg = ti[tt];
            if (tt < len)     sscore += pb[(size_t)tt * KK + tg];
            if (tt < len - 1) sscore += Trp[tg * 33 + ti[tt + 1]];
        }
        sscore = wsum(sscore);

        if (lane == 0)
            out[(size_t)BB * TT + BB + b] = sscore - log_norm;
    }
}

// =============================== Kernel 2: batch-transposed backtrace ===============================
// One warp handles 8 sequences; 4 lanes per sequence (lane = s*4+q, q owns candidates q*8..q*8+7).
__global__ __launch_bounds__(32)
void crf_backtrace_kernel(const float* __restrict__ trans,
                          const int*   __restrict__ seqlen,
                          float*       __restrict__ out)
{
    __shared__ float Ttr[KK][36];              // Ttr[j][i] = trans[i][j]
    __shared__ float buf[2][8][8][36];         // [stagebuf][step d][seq s][i]

    const int lane = threadIdx.x;
    const int sbase = blockIdx.x * 8;
    const int s = lane >> 2;                   // sequence-in-warp 0..7
    const int q = lane & 3;                    // candidate quarter 0..3
    const int seq = sbase + s;

    // transposed transitions into smem
    for (int idx = lane; idx < KK * KK; idx += 32) {
        int i = idx >> 5, j = idx & 31;
        Ttr[j][i] = trans[i * KK + j];
    }

    const int len  = seqlen[seq];
    int jcur = g_last[seq];
    const int lim = len - 2;                   // last backtrace step for this seq

    // uniform start: warp-max of lim
    int tmax = lim;
#pragma unroll
    for (int o = 16; o; o >>= 1)
        tmax = max(tmax, __shfl_xor_sync(FULLM, tmax, o));
    if (tmax < 0) return;                      // uniform: whole warp exits

    // stage prefetch: rows t = th, th-1, ..., th-7 for all 8 seqs
    const int pr = lane >> 2;                  // seq row loaded by this lane
    const int pc = (lane & 3) * 2;             // float4 chunk pair
    auto prefetch = [&](int th, int bsel) {
#pragma unroll
        for (int d = 0; d < 8; d++) {
            int t = th - d;
            if (t >= 0) {
                const float4* src = reinterpret_cast<const float4*>(
                    g_alpha + ((size_t)(sbase + pr) * TT + t) * KK);
                float4 v0 = __ldg(src + pc);
                float4 v1 = __ldg(src + pc + 1);
                *reinterpret_cast<float4*>(&buf[bsel][d][pr][pc * 4])     = v0;
                *reinterpret_cast<float4*>(&buf[bsel][d][pr][pc * 4 + 4]) = v1;
            }
        }
    };

    prefetch(tmax, 0);
    int cur = 0;

    for (int th = tmax; th >= 0; th -= 8) {
        __syncwarp();
        if (th - 8 >= 0) prefetch(th - 8, cur ^ 1);

#pragma unroll
        for (int d = 0; d < 8; d++) {
            int t = th - d;
            if (t < 0) break;                  // uniform (only in final stage)

            // local candidates i = q*8 .. q*8+7
            const float* ar = &buf[cur][d][s][q * 8];
            const float* tr = &Ttr[jcur][q * 8];
            float v[8];
#pragma unroll
            for (int k = 0; k < 8; k++) v[k] = ar[k] + tr[k];
            float m0 = fmaxf(v[0], v[1]), m1 = fmaxf(v[2], v[3]);
            float m2 = fmaxf(v[4], v[5]), m3 = fmaxf(v[6], v[7]);
            float best = fmaxf(fmaxf(m0, m1), fmaxf(m2, m3));
            int idx = 8;
#pragma unroll
            for (int k = 7; k >= 0; k--)
                if (v[k] == best) idx = k;     // lowest k wins (first-occurrence)
            float vbest = best;
            int ibest = q * 8 + idx;

            // combine across the 4 lanes of this sequence (xor 1, 2 stay in-group)
#pragma unroll
            for (int o = 1; o <= 2; o <<= 1) {
                float ov = __shfl_xor_sync(FULLM, vbest, o);
                int   oi = __shfl_xor_sync(FULLM, ibest, o);
                if (ov > vbest || (ov == vbest && oi < ibest)) { vbest = ov; ibest = oi; }
            }

            if (t <= lim) {                    // per-sequence predicate
                jcur = ibest;
                if (q == 0)
                    out[(size_t)seq * TT + t] = (float)jcur;
            }
        }
        cur ^= 1;
    }
}

extern "C" void kernel_launch(void* const* d_in, const int* in_sizes, int n_in,
                              void* d_out, int out_size) {
    const float* pot    = (const float*)d_in[0];
    const float* trans  = (const float*)d_in[1];
    const int*   seqlen = (const int*)d_in[2];
    const int*   tags   = (const int*)d_in[3];
    float* out = (float*)d_out;

    crf_forward_kernel<<<BB, 64>>>(pot, trans, seqlen, tags, out);
    crf_backtrace_kernel<<<BB / 8, 32>>>(trans, seqlen, out);
}

// round 14
// speedup vs baseline: 1.4458x; 1.1470x over previous
#include <cuda_runtime.h>
#include <cstdint>

#define BB 2048
#define TT 512
#define KK 32
#define FULLM 0xffffffffu

// 128 MB alpha-row scratch + last-tag handoff (device globals; no allocation)
__device__ float g_alpha[(size_t)BB * TT * KK];
__device__ int   g_last[BB];

// ---- packed f32x2 helpers
__device__ __forceinline__ unsigned long long add2(unsigned long long a, unsigned long long b) {
    unsigned long long r; asm("add.rn.f32x2 %0,%1,%2;" : "=l"(r) : "l"(a), "l"(b)); return r;
}
__device__ __forceinline__ unsigned long long fma2(unsigned long long a, unsigned long long b, unsigned long long c) {
    unsigned long long r; asm("fma.rn.f32x2 %0,%1,%2,%3;" : "=l"(r) : "l"(a), "l"(b), "l"(c)); return r;
}
__device__ __forceinline__ float2 unpk(unsigned long long a) {
    float2 f; asm("mov.b64 {%0,%1},%2;" : "=f"(f.x), "=f"(f.y) : "l"(a)); return f;
}
__device__ __forceinline__ unsigned long long pk(float x, float y) {
    unsigned long long r; asm("mov.b64 %0,{%1,%2};" : "=l"(r) : "f"(x), "f"(y)); return r;
}

__device__ __forceinline__ float wsum(float v) {
#pragma unroll
    for (int o = 16; o; o >>= 1)
        v += __shfl_xor_sync(FULLM, v, o);
    return v;
}

// max_i (row[i] + trc[i][lane]) using packed adds
__device__ __forceinline__ float rowmax(const float* __restrict__ row,
                                        const unsigned long long* __restrict__ trc2) {
    const ulonglong2* r2 = reinterpret_cast<const ulonglong2*>(row);
    float best = -3.402823466e38f;
#pragma unroll
    for (int c = 0; c < 4; c++) {
        ulonglong2 qa = r2[c];
        ulonglong2 qb = r2[c + 4];
        float2 f0 = unpk(add2(qa.x, trc2[2 * c + 0]));
        float2 f1 = unpk(add2(qa.y, trc2[2 * c + 1]));
        float2 f2 = unpk(add2(qb.x, trc2[2 * c + 8]));
        float2 f3 = unpk(add2(qb.y, trc2[2 * c + 9]));
        float m0 = fmaxf(fmaxf(f0.x, f0.y), fmaxf(f1.x, f1.y));
        float m1 = fmaxf(fmaxf(f2.x, f2.y), fmaxf(f3.x, f3.y));
        best = fmaxf(best, fmaxf(m0, m1));
    }
    return best;
}

// sum_i row[i] * etr[i][lane] using packed FMAs
__device__ __forceinline__ float rowdot(const float* __restrict__ row,
                                        const unsigned long long* __restrict__ etr2) {
    const ulonglong2* r2 = reinterpret_cast<const ulonglong2*>(row);
    unsigned long long a0 = 0ull, a1 = 0ull, a2 = 0ull, a3 = 0ull;
#pragma unroll
    for (int c = 0; c < 4; c++) {
        ulonglong2 qa = r2[c];
        ulonglong2 qb = r2[c + 4];
        a0 = fma2(qa.x, etr2[2 * c + 0], a0);
        a1 = fma2(qa.y, etr2[2 * c + 1], a1);
        a2 = fma2(qb.x, etr2[2 * c + 8], a2);
        a3 = fma2(qb.y, etr2[2 * c + 9], a3);
    }
    float2 s = unpk(add2(add2(a0, a1), add2(a2, a3)));
    return s.x + s.y;
}

// exact power-of-2 renormalization (shfl exponent max)
__device__ __forceinline__ void renorm(float& a, int& C) {
    int eb = (__float_as_int(a) >> 23) & 0xff;
#pragma unroll
    for (int o = 16; o; o >>= 1)
        eb = max(eb, __shfl_xor_sync(FULLM, eb, o));
    int de = eb - 127;
    C += de;
    a *= __int_as_float((127 - de) << 23);
}

__device__ __forceinline__ uint32_t smem_u32(const void* p) {
    uint32_t a;
    asm("{ .reg .u64 t; cvta.to.shared.u64 t, %1; cvt.u32.u64 %0, t; }" : "=r"(a) : "l"(p));
    return a;
}

// =============================== Kernel 1: forward passes ===============================
__global__ __launch_bounds__(64, 16)
void crf_forward_kernel(const float* __restrict__ pot,     // [B,T,K]
                        const float* __restrict__ trans,   // [K,K]
                        const int*   __restrict__ seqlen,  // [B]
                        const int*   __restrict__ tags_in, // [B,T]
                        float*       __restrict__ out)     // [B*T + 2B] f32
{
    __shared__ float Trp[KK * 33];                   // trans for seq-score
    __shared__ __align__(16) float vrow[2][KK];
    __shared__ __align__(16) float lrow[2][KK];

    const int tid  = threadIdx.x;
    const int lane = tid & 31;
    const int role = tid >> 5;          // 0 = viterbi fwd, 1 = partition
    const int b    = blockIdx.x;
    const int len  = seqlen[b];

    const float LOG2E = 1.4426950408889634f;
    const float* pb = pot + (size_t)b * TT * KK;
    float* out_tags = out;

    for (int idx = tid; idx < KK * KK; idx += 64)
        Trp[(idx >> 5) * 33 + (idx & 31)] = trans[idx];
    __syncthreads();

    if (role == 0) {
        // ---------------- Viterbi forward (value-only; alphas streamed) ----------------
        unsigned long long trc2[16];
#pragma unroll
        for (int k = 0; k < 16; k++)
            trc2[k] = pk(__ldg(&trans[(2 * k) * KK + lane]),
                         __ldg(&trans[(2 * k + 1) * KK + lane]));

        float* gab = g_alpha + (size_t)b * TT * KK;
        float alpha = pb[lane];

        int t = 1;
        for (; t + 1 < len; t += 2) {
            float pa = pb[(size_t)t * KK + lane];
            float pc = pb[(size_t)(t + 1) * KK + lane];
            gab[(size_t)(t - 1) * KK + lane] = alpha;
            vrow[0][lane] = alpha;
            __syncwarp();
            alpha = pa + rowmax(vrow[0], trc2);
            gab[(size_t)t * KK + lane] = alpha;
            vrow[1][lane] = alpha;
            __syncwarp();
            alpha = pc + rowmax(vrow[1], trc2);
        }
        if (t < len) {
            float pa = pb[(size_t)t * KK + lane];
            gab[(size_t)(t - 1) * KK + lane] = alpha;
            vrow[0][lane] = alpha;
            __syncwarp();
            alpha = pa + rowmax(vrow[0], trc2);
        }

        // last_tag / best_score: bundled shfl argmax (first-occurrence exact)
        float bv = alpha; int bi = lane;
#pragma unroll
        for (int o = 16; o; o >>= 1) {
            float ov = __shfl_xor_sync(FULLM, bv, o);
            int   oi = __shfl_xor_sync(FULLM, bi, o);
            if (ov > bv || (ov == bv && oi < bi)) { bv = ov; bi = oi; }
        }
        const int last_tag = bi;

        for (int tt = len - 1 + lane; tt < TT; tt += 32)
            out_tags[(size_t)b * TT + tt] = (float)last_tag;
        if (lane == 0) {
            out[(size_t)BB * TT + b] = bv;   // best_score
            g_last[b] = last_tag;            // handoff to backtrace kernel
        }
    } else {
        // ---------------- partition (linear domain) + seq-score ----------------
        unsigned long long etr2[16];
#pragma unroll
        for (int k = 0; k < 16; k++)
            etr2[k] = pk(exp2f(__ldg(&trans[(2 * k) * KK + lane]) * LOG2E),
                         exp2f(__ldg(&trans[(2 * k + 1) * KK + lane]) * LOG2E));

        float a = exp2f(pb[lane] * LOG2E);
        int C = 0;

        int t = 1;
        for (; t + 1 < len; t += 2) {
            float pa = pb[(size_t)t * KK + lane];
            float pc = pb[(size_t)(t + 1) * KK + lane];
            lrow[0][lane] = a;
            __syncwarp();
            a = exp2f(pa * LOG2E) * rowdot(lrow[0], etr2);
            lrow[1][lane] = a;
            __syncwarp();
            a = exp2f(pc * LOG2E) * rowdot(lrow[1], etr2);
            if (((t + 1) & 7) == 0)
                renorm(a, C);
        }
        if (t < len) {
            float pa = pb[(size_t)t * KK + lane];
            lrow[0][lane] = a;
            __syncwarp();
            a = exp2f(pa * LOG2E) * rowdot(lrow[0], etr2);
        }

        float s = wsum(a);
        float log_norm = (float)((double)C * 0.6931471805599453) + logf(s);

        const int* ti = tags_in + (size_t)b * TT;
        float sscore = 0.f;
        for (int tt = lane; tt < TT; tt += 32) {
            int tg = ti[tt];
            if (tt < len)     sscore += pb[(size_t)tt * KK + tg];
            if (tt < len - 1) sscore += Trp[tg * 33 + ti[tt + 1]];
        }
        sscore = wsum(sscore);

        if (lane == 0)
            out[(size_t)BB * TT + BB + b] = sscore - log_norm;
    }
}

// =============================== Kernel 2: batch-transposed backtrace ===============================
// One warp handles 8 sequences; 4 lanes per sequence. Alpha rows staged via cp.async (depth 3).
#define NSTG 4   // smem stage slots (3 in flight)

__global__ __launch_bounds__(32)
void crf_backtrace_kernel(const float* __restrict__ trans,
                          const int*   __restrict__ seqlen,
                          float*       __restrict__ out)
{
    __shared__ float Ttr[KK][36];                          // Ttr[j][i] = trans[i][j]
    __shared__ __align__(16) float buf[NSTG][8][8][36];    // [slot][step d][seq s][state i]

    const int lane  = threadIdx.x;
    const int sbase = blockIdx.x * 8;
    const int s = lane >> 2;                   // sequence-in-warp 0..7
    const int q = lane & 3;                    // candidate quarter 0..3
    const int seq = sbase + s;

    for (int idx = lane; idx < KK * KK; idx += 32) {
        int i = idx >> 5, j = idx & 31;
        Ttr[j][i] = trans[i * KK + j];
    }

    const int len = seqlen[seq];
    int jcur = g_last[seq];
    const int lim = len - 2;                   // last backtrace step for this seq

    int tmax = lim;
#pragma unroll
    for (int o = 16; o; o >>= 1)
        tmax = max(tmax, __shfl_xor_sync(FULLM, tmax, o));
    if (tmax < 0) return;                      // uniform: whole warp exits

    // issue one stage (8 rows x 8 seqs) via cp.async; ALWAYS commits exactly one group
    auto stage_issue = [&](int th, int ss) {
#pragma unroll
        for (int it = 0; it < 16; it++) {
            int c = it * 32 + lane;            // chunk 0..511
            int k   = c & 7;                   // 16B chunk within row
            int sdx = (c >> 3) & 7;            // seq
            int d   = c >> 6;                  // step 0..7
            int t = th - d;
            if (t >= 0) {
                const float* src = g_alpha + ((size_t)(sbase + sdx) * TT + t) * KK + k * 4;
                uint32_t dst = smem_u32(&buf[ss][d][sdx][k * 4]);
                asm volatile("cp.async.cg.shared.global [%0], [%1], 16;" :: "r"(dst), "l"(src));
            }
        }
        asm volatile("cp.async.commit_group;" ::: "memory");
    };

    const int nst = (tmax >> 3) + 1;           // number of stages

    // prologue: 3 committed groups (stages 0..2, empty commits beyond nst)
#pragma unroll
    for (int p = 0; p < 3; p++) {
        if (p < nst) stage_issue(tmax - 8 * p, p);
        else asm volatile("cp.async.commit_group;" ::: "memory");
    }

    for (int kst = 0; kst < nst; kst++) {
        int slot = kst & (NSTG - 1);
        // keep 3 groups in flight: issue stage kst+3 (slot reuse is safe: == slot of kst-1)
        if (kst + 3 < nst) stage_issue(tmax - 8 * (kst + 3), (kst + 3) & (NSTG - 1));
        else asm volatile("cp.async.commit_group;" ::: "memory");

        // after this, total groups = kst+4; wait_group 3 => stages <= kst complete
        asm volatile("cp.async.wait_group 3;" ::: "memory");
        __syncwarp();

#pragma unroll
        for (int d = 0; d < 8; d++) {
            int t = tmax - 8 * kst - d;
            if (t < 0) break;                  // warp-uniform (final stage only)

            const float* ar = &buf[slot][d][s][q * 8];
            const float* tr = &Ttr[jcur][q * 8];
            float v[8];
#pragma unroll
            for (int k = 0; k < 8; k++) v[k] = ar[k] + tr[k];
            float m0 = fmaxf(v[0], v[1]), m1 = fmaxf(v[2], v[3]);
            float m2 = fmaxf(v[4], v[5]), m3 = fmaxf(v[6], v[7]);
            float best = fmaxf(fmaxf(m0, m1), fmaxf(m2, m3));
            int idx = 0;
#pragma unroll
            for (int k = 7; k >= 0; k--)
                if (v[k] == best) idx = k;     // lowest k wins (first-occurrence)
            float vbest = best;
            int ibest = q * 8 + idx;

            // combine across the 4 lanes of this sequence (xor 1,2 stay in-group)
#pragma unroll
            for (int o = 1; o <= 2; o <<= 1) {
                float ov = __shfl_xor_sync(FULLM, vbest, o);
                int   oi = __shfl_xor_sync(FULLM, ibest, o);
                if (ov > vbest || (ov == vbest && oi < ibest)) { vbest = ov; ibest = oi; }
            }

            if (t <= lim) {                    // per-sequence predicate
                jcur = ibest;
                if (q == 0)
                    out[(size_t)seq * TT + t] = (float)jcur;
            }
        }
        __syncwarp();                          // slot consumed before refill next iters
    }
}

extern "C" void kernel_launch(void* const* d_in, const int* in_sizes, int n_in,
                              void* d_out, int out_size) {
    const float* pot    = (const float*)d_in[0];
    const float* trans  = (const float*)d_in[1];
    const int*   seqlen = (const int*)d_in[2];
    const int*   tags   = (const int*)d_in[3];
    float* out = (float*)d_out;

    crf_forward_kernel<<<BB, 64>>>(pot, trans, seqlen, tags, out);
    crf_backtrace_kernel<<<BB / 8, 32>>>(trans, seqlen, out);
}